// round 2
// baseline (speedup 1.0000x reference)
#include <cuda_runtime.h>
#include <cuda_bf16.h>

// Depthwise conv1d, fixed shape: B=4, D=2048, L=8192, K=3, pad=1 -> L_out=L.
// out[b,d,l] = bias[d] + w[d,0]*x[l-1] + w[d,1]*x[l] + w[d,2]*x[l+1]
//
// HBM-streaming kernel, 16 contiguous elements (4x float4) per thread.
// Interior halos come from registers; only 2 scalar halo loads per 16
// outputs (cache-resident sectors). Weights/bias uniform per block.

#define CONV_B 4
#define CONV_D 2048
#define CONV_L 8192
#define ELEMS_PER_THREAD 16

__global__ __launch_bounds__(256) void dwconv1d_k3_kernel(
    const float* __restrict__ x,     // [B*D, L]
    const float* __restrict__ w,     // [D, 3]
    const float* __restrict__ bias,  // [D]
    float* __restrict__ out)         // [B*D, L]
{
    // one thread = 16 contiguous elements; grid sized exactly, no loop
    const unsigned tid  = blockIdx.x * blockDim.x + threadIdx.x;
    const unsigned base = tid * ELEMS_PER_THREAD;          // element index, < 2^27

    const unsigned l = base & (CONV_L - 1);                // pos within row
    const unsigned d = (base >> 13) & (CONV_D - 1);        // channel

    // uniform within the block (block spans 4096 elems inside one row)
    const float w0 = __ldg(&w[d * 3 + 0]);
    const float w1 = __ldg(&w[d * 3 + 1]);
    const float w2 = __ldg(&w[d * 3 + 2]);
    const float bv = __ldg(&bias[d]);

    // 4 independent 128-bit loads, issued back-to-back (MLP)
    const float4* xv = reinterpret_cast<const float4*>(x + base);
    float4 v0 = xv[0];
    float4 v1 = xv[1];
    float4 v2 = xv[2];
    float4 v3 = xv[3];

    // halo loads: hit sectors fetched by neighboring threads (L1/L2)
    const float left  = (l > 0) ? __ldg(x + base - 1) : 0.0f;
    const float right = (l + ELEMS_PER_THREAD < CONV_L)
                        ? __ldg(x + base + ELEMS_PER_THREAD) : 0.0f;

    float4 o0, o1, o2, o3;
    // quad 0
    o0.x = fmaf(w0, left,  fmaf(w1, v0.x, fmaf(w2, v0.y, bv)));
    o0.y = fmaf(w0, v0.x, fmaf(w1, v0.y, fmaf(w2, v0.z, bv)));
    o0.z = fmaf(w0, v0.y, fmaf(w1, v0.z, fmaf(w2, v0.w, bv)));
    o0.w = fmaf(w0, v0.z, fmaf(w1, v0.w, fmaf(w2, v1.x, bv)));
    // quad 1
    o1.x = fmaf(w0, v0.w, fmaf(w1, v1.x, fmaf(w2, v1.y, bv)));
    o1.y = fmaf(w0, v1.x, fmaf(w1, v1.y, fmaf(w2, v1.z, bv)));
    o1.z = fmaf(w0, v1.y, fmaf(w1, v1.z, fmaf(w2, v1.w, bv)));
    o1.w = fmaf(w0, v1.z, fmaf(w1, v1.w, fmaf(w2, v2.x, bv)));
    // quad 2
    o2.x = fmaf(w0, v1.w, fmaf(w1, v2.x, fmaf(w2, v2.y, bv)));
    o2.y = fmaf(w0, v2.x, fmaf(w1, v2.y, fmaf(w2, v2.z, bv)));
    o2.z = fmaf(w0, v2.y, fmaf(w1, v2.z, fmaf(w2, v2.w, bv)));
    o2.w = fmaf(w0, v2.z, fmaf(w1, v2.w, fmaf(w2, v3.x, bv)));
    // quad 3
    o3.x = fmaf(w0, v2.w, fmaf(w1, v3.x, fmaf(w2, v3.y, bv)));
    o3.y = fmaf(w0, v3.x, fmaf(w1, v3.y, fmaf(w2, v3.z, bv)));
    o3.z = fmaf(w0, v3.y, fmaf(w1, v3.z, fmaf(w2, v3.w, bv)));
    o3.w = fmaf(w0, v3.z, fmaf(w1, v3.w, fmaf(w2, right, bv)));

    // streaming stores — no reuse, evict-first
    float4* ov = reinterpret_cast<float4*>(out + base);
    __stcs(&ov[0], o0);
    __stcs(&ov[1], o1);
    __stcs(&ov[2], o2);
    __stcs(&ov[3], o3);
}

extern "C" void kernel_launch(void* const* d_in, const int* in_sizes, int n_in,
                              void* d_out, int out_size)
{
    const float* x    = (const float*)d_in[0];
    const float* w    = (const float*)d_in[1];
    const float* bias = (const float*)d_in[2];
    float*       out  = (float*)d_out;

    const long long total = (long long)CONV_B * CONV_D * CONV_L;   // 67.1M
    const int threads = 256;
    const int blocks  = (int)(total / (threads * ELEMS_PER_THREAD)); // 16384

    dwconv1d_k3_kernel<<<blocks, threads>>>(x, w, bias, out);
}

// round 3
// speedup vs baseline: 1.1457x; 1.1457x over previous
#include <cuda_runtime.h>
#include <cuda_bf16.h>

// Depthwise conv1d, fixed shape: B=4, D=2048, L=8192, K=3, pad=1 -> L_out=L.
// out[b,d,l] = bias[d] + w[d,0]*x[l-1] + w[d,1]*x[l] + w[d,2]*x[l+1]
//
// 16 contiguous elements (4x float4) per thread. Halos come from warp
// shuffles (neighbor lanes hold them in registers); only the 2 warp-edge
// lanes touch memory for halos (1 L1 wavefront each). A warp covers 512
// contiguous elements and never straddles a row (512 | 8192).

#define CONV_B 4
#define CONV_D 2048
#define CONV_L 8192
#define ELEMS_PER_THREAD 16

__global__ __launch_bounds__(256) void dwconv1d_k3_kernel(
    const float* __restrict__ x,     // [B*D, L]
    const float* __restrict__ w,     // [D, 3]
    const float* __restrict__ bias,  // [D]
    float* __restrict__ out)         // [B*D, L]
{
    const unsigned tid  = blockIdx.x * blockDim.x + threadIdx.x;
    const unsigned base = tid * ELEMS_PER_THREAD;           // < 2^27
    const unsigned lane = threadIdx.x & 31;

    const unsigned l = base & (CONV_L - 1);                 // pos within row
    const unsigned d = (base >> 13) & (CONV_D - 1);         // channel

    // uniform within the block (block spans 4096 elems inside one row)
    const float w0 = __ldg(&w[d * 3 + 0]);
    const float w1 = __ldg(&w[d * 3 + 1]);
    const float w2 = __ldg(&w[d * 3 + 2]);
    const float bv = __ldg(&bias[d]);

    // 4 independent 128-bit loads (MLP)
    const float4* xv = reinterpret_cast<const float4*>(x + base);
    float4 v0 = xv[0];
    float4 v1 = xv[1];
    float4 v2 = xv[2];
    float4 v3 = xv[3];

    // halos via shuffle: lane-1 holds element base-1 (its v3.w),
    // lane+1 holds element base+16 (its v0.x)
    float left  = __shfl_up_sync(0xffffffffu, v3.w, 1);
    float right = __shfl_down_sync(0xffffffffu, v0.x, 1);
    if (lane == 0)
        left  = (l > 0) ? __ldg(x + base - 1) : 0.0f;
    if (lane == 31)
        right = (l + ELEMS_PER_THREAD < CONV_L) ? __ldg(x + base + ELEMS_PER_THREAD) : 0.0f;

    float4 o0, o1, o2, o3;
    // quad 0
    o0.x = fmaf(w0, left,  fmaf(w1, v0.x, fmaf(w2, v0.y, bv)));
    o0.y = fmaf(w0, v0.x, fmaf(w1, v0.y, fmaf(w2, v0.z, bv)));
    o0.z = fmaf(w0, v0.y, fmaf(w1, v0.z, fmaf(w2, v0.w, bv)));
    o0.w = fmaf(w0, v0.z, fmaf(w1, v0.w, fmaf(w2, v1.x, bv)));
    // quad 1
    o1.x = fmaf(w0, v0.w, fmaf(w1, v1.x, fmaf(w2, v1.y, bv)));
    o1.y = fmaf(w0, v1.x, fmaf(w1, v1.y, fmaf(w2, v1.z, bv)));
    o1.z = fmaf(w0, v1.y, fmaf(w1, v1.z, fmaf(w2, v1.w, bv)));
    o1.w = fmaf(w0, v1.z, fmaf(w1, v1.w, fmaf(w2, v2.x, bv)));
    // quad 2
    o2.x = fmaf(w0, v1.w, fmaf(w1, v2.x, fmaf(w2, v2.y, bv)));
    o2.y = fmaf(w0, v2.x, fmaf(w1, v2.y, fmaf(w2, v2.z, bv)));
    o2.z = fmaf(w0, v2.y, fmaf(w1, v2.z, fmaf(w2, v2.w, bv)));
    o2.w = fmaf(w0, v2.z, fmaf(w1, v2.w, fmaf(w2, v3.x, bv)));
    // quad 3
    o3.x = fmaf(w0, v2.w, fmaf(w1, v3.x, fmaf(w2, v3.y, bv)));
    o3.y = fmaf(w0, v3.x, fmaf(w1, v3.y, fmaf(w2, v3.z, bv)));
    o3.z = fmaf(w0, v3.y, fmaf(w1, v3.z, fmaf(w2, v3.w, bv)));
    o3.w = fmaf(w0, v3.z, fmaf(w1, v3.w, fmaf(w2, right, bv)));

    // streaming stores — no reuse, evict-first
    float4* ov = reinterpret_cast<float4*>(out + base);
    __stcs(&ov[0], o0);
    __stcs(&ov[1], o1);
    __stcs(&ov[2], o2);
    __stcs(&ov[3], o3);
}

extern "C" void kernel_launch(void* const* d_in, const int* in_sizes, int n_in,
                              void* d_out, int out_size)
{
    const float* x    = (const float*)d_in[0];
    const float* w    = (const float*)d_in[1];
    const float* bias = (const float*)d_in[2];
    float*       out  = (float*)d_out;

    const long long total = (long long)CONV_B * CONV_D * CONV_L;   // 67.1M
    const int threads = 256;
    const int blocks  = (int)(total / (threads * ELEMS_PER_THREAD)); // 16384

    dwconv1d_k3_kernel<<<blocks, threads>>>(x, w, bias, out);
}

// round 4
// speedup vs baseline: 1.2249x; 1.0691x over previous
#include <cuda_runtime.h>
#include <cuda_bf16.h>

// Depthwise conv1d, fixed shape: B=4, D=2048, L=8192, K=3, pad=1 -> L_out=L.
// out[b,d,l] = bias[d] + w[d,0]*x[l-1] + w[d,1]*x[l] + w[d,2]*x[l+1]
//
// 8 contiguous elements (2x float4) per thread. Halos via warp shuffle;
// only warp-edge lanes touch memory for halos. Warp = 256 contiguous
// elements, never straddles a row (256 | 8192).

#define CONV_B 4
#define CONV_D 2048
#define CONV_L 8192
#define ELEMS_PER_THREAD 8

__global__ __launch_bounds__(256) void dwconv1d_k3_kernel(
    const float* __restrict__ x,     // [B*D, L]
    const float* __restrict__ w,     // [D, 3]
    const float* __restrict__ bias,  // [D]
    float* __restrict__ out)         // [B*D, L]
{
    const unsigned tid  = blockIdx.x * blockDim.x + threadIdx.x;
    const unsigned base = tid * ELEMS_PER_THREAD;           // < 2^27
    const unsigned lane = threadIdx.x & 31;

    const unsigned l = base & (CONV_L - 1);                 // pos within row
    const unsigned d = (base >> 13) & (CONV_D - 1);         // channel

    // uniform within the block (block spans 2048 elems inside one row)
    const float w0 = __ldg(&w[d * 3 + 0]);
    const float w1 = __ldg(&w[d * 3 + 1]);
    const float w2 = __ldg(&w[d * 3 + 2]);
    const float bv = __ldg(&bias[d]);

    // 2 independent 128-bit loads
    const float4* xv = reinterpret_cast<const float4*>(x + base);
    float4 v0 = xv[0];
    float4 v1 = xv[1];

    // halos via shuffle: lane-1 holds element base-1 (its v1.w),
    // lane+1 holds element base+8 (its v0.x)
    float left  = __shfl_up_sync(0xffffffffu, v1.w, 1);
    float right = __shfl_down_sync(0xffffffffu, v0.x, 1);
    if (lane == 0)
        left  = (l > 0) ? __ldg(x + base - 1) : 0.0f;
    if (lane == 31)
        right = (l + ELEMS_PER_THREAD < CONV_L) ? __ldg(x + base + ELEMS_PER_THREAD) : 0.0f;

    float4 o0, o1;
    o0.x = fmaf(w0, left,  fmaf(w1, v0.x, fmaf(w2, v0.y, bv)));
    o0.y = fmaf(w0, v0.x, fmaf(w1, v0.y, fmaf(w2, v0.z, bv)));
    o0.z = fmaf(w0, v0.y, fmaf(w1, v0.z, fmaf(w2, v0.w, bv)));
    o0.w = fmaf(w0, v0.z, fmaf(w1, v0.w, fmaf(w2, v1.x, bv)));

    o1.x = fmaf(w0, v0.w, fmaf(w1, v1.x, fmaf(w2, v1.y, bv)));
    o1.y = fmaf(w0, v1.x, fmaf(w1, v1.y, fmaf(w2, v1.z, bv)));
    o1.z = fmaf(w0, v1.y, fmaf(w1, v1.z, fmaf(w2, v1.w, bv)));
    o1.w = fmaf(w0, v1.z, fmaf(w1, v1.w, fmaf(w2, right, bv)));

    // streaming stores — no reuse, evict-first
    float4* ov = reinterpret_cast<float4*>(out + base);
    __stcs(&ov[0], o0);
    __stcs(&ov[1], o1);
}

extern "C" void kernel_launch(void* const* d_in, const int* in_sizes, int n_in,
                              void* d_out, int out_size)
{
    const float* x    = (const float*)d_in[0];
    const float* w    = (const float*)d_in[1];
    const float* bias = (const float*)d_in[2];
    float*       out  = (float*)d_out;

    const long long total = (long long)CONV_B * CONV_D * CONV_L;     // 67.1M
    const int threads = 256;
    const int blocks  = (int)(total / (threads * ELEMS_PER_THREAD)); // 32768

    dwconv1d_k3_kernel<<<blocks, threads>>>(x, w, bias, out);
}